// round 4
// baseline (speedup 1.0000x reference)
#include <cuda_runtime.h>
#include <math.h>

#define B 64
#define H 80
#define W 80
#define C 80
#define CP 84
#define K 100
#define CAND_MAX 131072
#define EQCAP 2048
#define SELCAP 128
#define SLICES 4

// pk = (float_bits(score) << 32) | ~sidx : plain u64 '>' == (score desc, idx asc),
// matching jax stable argsort of -score.
__device__ unsigned long long g_cand[B][CAND_MAX];
__device__ int g_hist[B][65536];
__device__ unsigned long long g_sel[B][SELCAP];
__device__ unsigned long long g_eq[B][EQCAP];
__device__ int g_cnt[B * 32];
__device__ int g_selcnt[B * 32];
__device__ int g_eqcnt[B * 32];
__device__ int g_tbin[B * 32];

// ---------------------------------------------------------------------------
// K1: 3x3 NMS peaks. One thread = 4 channels at one (b,i,j); 9 float4 loads.
// threads = B*H*W*(C/4) = 8,192,000; blocks have uniform b (500 blocks/batch).
__global__ void peaks_kernel(const float* __restrict__ y) {
    __shared__ int s_total;
    __shared__ int s_base;
    if (threadIdx.x == 0) s_total = 0;
    __syncthreads();

    int t = blockIdx.x * blockDim.x + threadIdx.x;
    int cg   = t % (C / 4);
    int s    = t / (C / 4);
    int j    = s % W;
    int rest = s / W;
    int i    = rest % H;
    int b    = rest / H;
    int c0   = cg * 4;

    const float* base = y + ((size_t)((b * H + i) * W + j)) * CP + c0;
    float4 v = *(const float4*)base;
    float4 m = v;

    #pragma unroll
    for (int di = -1; di <= 1; ++di) {
        int ii = i + di;
        if (ii < 0 || ii >= H) continue;
        #pragma unroll
        for (int dj = -1; dj <= 1; ++dj) {
            if (di == 0 && dj == 0) continue;
            int jj = j + dj;
            if (jj < 0 || jj >= W) continue;
            float4 nb = *(const float4*)(base + (di * W + dj) * CP);
            m.x = fmaxf(m.x, nb.x);
            m.y = fmaxf(m.y, nb.y);
            m.z = fmaxf(m.z, nb.z);
            m.w = fmaxf(m.w, nb.w);
        }
    }

    float vv[4] = {v.x, v.y, v.z, v.w};
    float mm[4] = {m.x, m.y, m.z, m.w};
    unsigned long long pk[4]; int cnt = 0;
    int sidx = (i * W + j) * C + c0;
    #pragma unroll
    for (int q = 0; q < 4; ++q) {
        if (vv[q] == mm[q] && vv[q] > 0.0f) {
            unsigned key = __float_as_uint(vv[q]);
            pk[cnt] = ((unsigned long long)key << 32) | (unsigned)(~(unsigned)(sidx + q));
            cnt++;
        }
    }

    // warp prefix + one global atomic per block
    int lane = threadIdx.x & 31;
    int incl = cnt;
    #pragma unroll
    for (int d = 1; d < 32; d <<= 1) {
        int o = __shfl_up_sync(0xffffffffu, incl, d);
        if (lane >= d) incl += o;
    }
    int wtotal = __shfl_sync(0xffffffffu, incl, 31);
    int wbase = 0;
    if (lane == 31 && wtotal > 0) wbase = atomicAdd(&s_total, wtotal);
    wbase = __shfl_sync(0xffffffffu, wbase, 31);
    __syncthreads();
    if (threadIdx.x == 0) {
        int bt = s_total;
        s_base = (bt > 0) ? atomicAdd(&g_cnt[b * 32], bt) : 0;
    }
    __syncthreads();

    int off = s_base + wbase + incl - cnt;
    for (int q = 0; q < cnt; ++q) {
        int p = off + q;
        if (p < CAND_MAX) {
            g_cand[b][p] = pk[q];
            atomicAdd(&g_hist[b][(unsigned)(pk[q] >> 48)], 1);
        }
    }
}

// ---------------------------------------------------------------------------
// K2: exact K-th-largest 16-bit bin from histogram. Coalesced warp-per-chunk.
__global__ void threshold_kernel() {
    int b = blockIdx.x;
    int tid = threadIdx.x;             // 256
    int lane = tid & 31, w = tid >> 5;
    const int* hb = g_hist[b];

    __shared__ int sums[256];
    __shared__ int s_above, s_wc, s_tbin;

    // chunk c covers bins [c*256, c*256+256); lane loads 8 contiguous ints.
    for (int c = w; c < 256; c += 8) {
        const int4* p = (const int4*)(hb + c * 256 + lane * 8);
        int4 a = p[0], bb = p[1];
        int sm = a.x + a.y + a.z + a.w + bb.x + bb.y + bb.z + bb.w;
        #pragma unroll
        for (int d = 16; d; d >>= 1) sm += __shfl_down_sync(0xffffffffu, sm, d);
        if (lane == 0) sums[c] = sm;
    }
    __syncthreads();

    if (tid == 0) {
        int acc = 0, wc = -1, ab = 0;
        for (int c = 255; c >= 0; --c) {
            if (acc + sums[c] >= K) { wc = c; ab = acc; break; }
            acc += sums[c];
        }
        s_wc = wc; s_above = ab; s_tbin = -1;
    }
    __syncthreads();

    int wc = s_wc;
    if (w == 0 && wc >= 0) {
        const int4* p = (const int4*)(hb + wc * 256 + lane * 8);
        int4 a = p[0], bb = p[1];
        int h[8] = {a.x, a.y, a.z, a.w, bb.x, bb.y, bb.z, bb.w};
        int ls = 0;
        #pragma unroll
        for (int q = 0; q < 8; ++q) ls += h[q];
        // inclusive suffix over lanes -> exclusive
        int x = ls;
        #pragma unroll
        for (int d = 1; d < 32; d <<= 1) {
            int o = __shfl_down_sync(0xffffffffu, x, d);
            if (lane + d < 32) x += o;
        }
        int acc = s_above + (x - ls);   // count strictly above my top bin
        #pragma unroll
        for (int q = 7; q >= 0; --q) {
            if (acc < K && acc + h[q] >= K) s_tbin = wc * 256 + lane * 8 + q;
            acc += h[q];
        }
    }
    __syncthreads();
    if (tid == 0) g_tbin[b * 32] = s_tbin;
}

// ---------------------------------------------------------------------------
// K2b: zero the 16MB histogram for the next replay, fully coalesced.
__global__ void zero_hist_kernel() {
    int idx = blockIdx.x * blockDim.x + threadIdx.x;
    ((int4*)g_hist)[idx] = make_int4(0, 0, 0, 0);
}

// ---------------------------------------------------------------------------
// K3: one scan of candidates -> above-threshold list (<K) + threshold-bin list.
__global__ void compact_kernel() {
    int bs = blockIdx.x;
    int b  = bs / SLICES;
    int sl = bs % SLICES;
    int n  = g_cnt[b * 32]; if (n > CAND_MAX) n = CAND_MAX;
    int tb = g_tbin[b * 32];

    int per = (n + SLICES - 1) / SLICES;
    int lo = sl * per;
    int hi = lo + per; if (hi > n) hi = n;

    for (int p = lo + threadIdx.x; p < hi; p += blockDim.x) {
        unsigned long long pk = g_cand[b][p];
        int bin = (int)(pk >> 48);
        if (bin > tb) {
            int q = atomicAdd(&g_selcnt[b * 32], 1);
            if (q < SELCAP) g_sel[b][q] = pk;
        } else if (bin == tb) {
            int q = atomicAdd(&g_eqcnt[b * 32], 1);
            if (q < EQCAP) g_eq[b][q] = pk;
        }
    }
}

// ---------------------------------------------------------------------------
// K4: exact rank of <=K entries + ties, gather from y, emit, reset counters.
__global__ void emit_kernel(const float* __restrict__ y, float* __restrict__ out) {
    int b = blockIdx.x;
    int tid = threadIdx.x;             // 256

    __shared__ unsigned long long a[K];
    __shared__ unsigned long long se[EQCAP];

    int mA = g_selcnt[b * 32]; if (mA > SELCAP) mA = SELCAP; if (mA > K) mA = K;
    int nE = g_eqcnt[b * 32];  if (nE > EQCAP) nE = EQCAP;
    int take = K - mA; if (take > nE) take = nE;

    if (tid < mA) a[tid] = g_sel[b][tid];
    for (int e = tid; e < nE; e += blockDim.x) se[e] = g_eq[b][e];
    __syncthreads();

    for (int e = tid; e < nE; e += blockDim.x) {
        unsigned long long mine = se[e];
        int r = 0;
        for (int q = 0; q < nE; ++q) r += (se[q] > mine) ? 1 : 0;
        if (r < take) a[mA + r] = mine;
    }
    __syncthreads();

    int M = mA + take;                 // == K normally

    float* score_out = out;
    float* k_out     = out + B * K;
    float* c_out     = out + 2 * B * K;
    float* w_out     = out + 4 * B * K;

    if (tid < M) {
        unsigned long long mine = a[tid];
        int r = 0;
        for (int q = 0; q < M; ++q) r += (a[q] > mine) ? 1 : 0;

        int fi  = (int)(~(unsigned)(mine & 0xffffffffu));
        float sc = __uint_as_float((unsigned)(mine >> 32));
        int kk  = fi % C;
        int rem = fi / C;
        int jj  = rem % W;
        int ii  = rem / W;
        const float* p = y + ((size_t)((b * H + ii) * W + jj)) * CP;
        float whx = 4.0f * (expf(p[C])     - 1.0f);
        float why = 4.0f * (expf(p[C + 1]) - 1.0f);
        float cx  = 4.0f * (float)jj + p[C + 2];
        float cy  = 4.0f * (float)ii + p[C + 3];

        score_out[b * K + r] = sc;
        k_out[b * K + r]     = (float)kk;
        c_out[(b * K + r) * 2 + 0] = cx;
        c_out[(b * K + r) * 2 + 1] = cy;
        w_out[(b * K + r) * 2 + 0] = whx;
        w_out[(b * K + r) * 2 + 1] = why;
    }

    for (int r = M + tid; r < K; r += blockDim.x) {   // degenerate pad only
        score_out[b * K + r] = 0.0f;
        k_out[b * K + r]     = 0.0f;
        c_out[(b * K + r) * 2 + 0] = 0.0f;
        c_out[(b * K + r) * 2 + 1] = 0.0f;
        w_out[(b * K + r) * 2 + 0] = 0.0f;
        w_out[(b * K + r) * 2 + 1] = 0.0f;
    }

    __syncthreads();
    if (tid == 0) {
        g_cnt[b * 32] = 0;
        g_selcnt[b * 32] = 0;
        g_eqcnt[b * 32] = 0;
    }
}

extern "C" void kernel_launch(void* const* d_in, const int* in_sizes, int n_in,
                              void* d_out, int out_size) {
    const float* yp = (const float*)d_in[0];
    float* out = (float*)d_out;

    int total = B * H * W * (C / 4);           // 8,192,000 threads
    peaks_kernel<<<total / 256, 256>>>(yp);
    threshold_kernel<<<B, 256>>>();
    zero_hist_kernel<<<(B * 65536 / 4) / 256, 256>>>();
    compact_kernel<<<B * SLICES, 256>>>();
    emit_kernel<<<B, 256>>>(yp, out);
}

// round 5
// speedup vs baseline: 2.0609x; 2.0609x over previous
#include <cuda_runtime.h>
#include <math.h>

#define B 64
#define H 80
#define W 80
#define C 80
#define CP 84
#define K 100
#define CAND_MAX 131072
#define NBINS 8192       // key>>18; positive float keys < 0x7F800000 -> bin < 8160
#define EQCAP 1024

// pk = (float_bits(score) << 32) | ~sidx : plain u64 '>' == (score desc, idx asc),
// matching jax stable argsort of -score.
__device__ unsigned long long g_cand[B][CAND_MAX];
__device__ int g_cnt[B * 32];

// ---------------------------------------------------------------------------
// K1: 3x3 NMS peaks. One thread = 4 channels at one (b,i,j); 9 float4 loads.
// threads = B*H*W*(C/4) = 8,192,000; blocks have uniform b.
__global__ void peaks_kernel(const float* __restrict__ y) {
    __shared__ int s_total;
    __shared__ int s_base;
    if (threadIdx.x == 0) s_total = 0;
    __syncthreads();

    int t = blockIdx.x * blockDim.x + threadIdx.x;
    int cg   = t % (C / 4);
    int s    = t / (C / 4);
    int j    = s % W;
    int rest = s / W;
    int i    = rest % H;
    int b    = rest / H;
    int c0   = cg * 4;

    const float* base = y + ((size_t)((b * H + i) * W + j)) * CP + c0;
    float4 v = *(const float4*)base;
    float4 m = v;

    #pragma unroll
    for (int di = -1; di <= 1; ++di) {
        int ii = i + di;
        if (ii < 0 || ii >= H) continue;
        #pragma unroll
        for (int dj = -1; dj <= 1; ++dj) {
            if (di == 0 && dj == 0) continue;
            int jj = j + dj;
            if (jj < 0 || jj >= W) continue;
            float4 nb = *(const float4*)(base + (di * W + dj) * CP);
            m.x = fmaxf(m.x, nb.x);
            m.y = fmaxf(m.y, nb.y);
            m.z = fmaxf(m.z, nb.z);
            m.w = fmaxf(m.w, nb.w);
        }
    }

    float vv[4] = {v.x, v.y, v.z, v.w};
    float mm[4] = {m.x, m.y, m.z, m.w};
    unsigned long long pk[4]; int cnt = 0;
    int sidx = (i * W + j) * C + c0;
    #pragma unroll
    for (int q = 0; q < 4; ++q) {
        if (vv[q] == mm[q] && vv[q] > 0.0f) {
            unsigned key = __float_as_uint(vv[q]);
            pk[cnt] = ((unsigned long long)key << 32) | (unsigned)(~(unsigned)(sidx + q));
            cnt++;
        }
    }

    // warp prefix + one global atomic per block
    int lane = threadIdx.x & 31;
    int incl = cnt;
    #pragma unroll
    for (int d = 1; d < 32; d <<= 1) {
        int o = __shfl_up_sync(0xffffffffu, incl, d);
        if (lane >= d) incl += o;
    }
    int wtotal = __shfl_sync(0xffffffffu, incl, 31);
    int wbase = 0;
    if (lane == 31 && wtotal > 0) wbase = atomicAdd(&s_total, wtotal);
    wbase = __shfl_sync(0xffffffffu, wbase, 31);
    __syncthreads();
    if (threadIdx.x == 0) {
        int bt = s_total;
        s_base = (bt > 0) ? atomicAdd(&g_cnt[b * 32], bt) : 0;
    }
    __syncthreads();

    int off = s_base + wbase + incl - cnt;
    for (int q = 0; q < cnt; ++q) {
        int p = off + q;
        if (p < CAND_MAX) g_cand[b][p] = pk[q];
    }
}

// ---------------------------------------------------------------------------
// K2: one block per batch does EVERYTHING: smem histogram -> exact K-th
// threshold bin -> compact (> and ==) -> exact rank -> gather -> emit.
__global__ void __launch_bounds__(512) select_kernel(const float* __restrict__ y,
                                                     float* __restrict__ out) {
    __shared__ int hist[NBINS];                 // 32KB
    __shared__ unsigned long long se[EQCAP];    // 8KB
    __shared__ unsigned long long a[K];
    __shared__ int csums[512];
    __shared__ int s_tbin, s_cA, s_cE;

    int b   = blockIdx.x;
    int tid = threadIdx.x;                      // 512 threads
    int n   = g_cnt[b * 32];
    if (n > CAND_MAX) n = CAND_MAX;
    const unsigned long long* cand = g_cand[b];

    #pragma unroll
    for (int i = tid; i < NBINS; i += 512) hist[i] = 0;
    if (tid == 0) { s_cA = 0; s_cE = 0; }
    __syncthreads();

    // pass 1: histogram of key>>18
    #pragma unroll 4
    for (int p = tid; p < n; p += 512)
        atomicAdd(&hist[(int)(cand[p] >> 50)], 1);
    __syncthreads();

    // per-thread chunk sums (16 bins each)
    {
        int s = 0, base = tid * 16;
        #pragma unroll
        for (int q = 0; q < 16; ++q) s += hist[base + q];
        csums[tid] = s;
    }
    __syncthreads();

    if (tid == 0) {
        int acc = 0, tb = -1;
        for (int c = 511; c >= 0; --c) {
            if (acc + csums[c] >= K) {
                int base = c * 16;
                for (int q = 15; q >= 0; --q) {
                    int h = hist[base + q];
                    if (acc + h >= K) { tb = base + q; break; }
                    acc += h;
                }
                break;
            }
            acc += csums[c];
        }
        s_tbin = tb;          // -1 => n < K: take everything
    }
    __syncthreads();
    int tb = s_tbin;

    // pass 2: compact into above-list (<K) and tie-list
    #pragma unroll 4
    for (int p = tid; p < n; p += 512) {
        unsigned long long pk = cand[p];
        int bin = (int)(pk >> 50);
        if (bin > tb) {
            int q = atomicAdd(&s_cA, 1);
            if (q < K) a[q] = pk;
        } else if (bin == tb) {
            int q = atomicAdd(&s_cE, 1);
            if (q < EQCAP) se[q] = pk;
        }
    }
    __syncthreads();

    int mA = s_cA; if (mA > K) mA = K;
    int nE = s_cE; if (nE > EQCAP) nE = EQCAP;
    int take = K - mA; if (take > nE) take = nE;

    // ties: top 'take' by (score desc, idx asc) == largest packed
    for (int e = tid; e < nE; e += 512) {
        unsigned long long mine = se[e];
        int r = 0;
        for (int q = 0; q < nE; ++q) r += (se[q] > mine) ? 1 : 0;
        if (r < take) a[mA + r] = mine;
    }
    __syncthreads();

    int M = mA + take;                           // == K normally

    float* score_out = out;
    float* k_out     = out + B * K;
    float* c_out     = out + 2 * B * K;
    float* w_out     = out + 4 * B * K;

    if (tid < M) {
        unsigned long long mine = a[tid];
        int r = 0;
        for (int q = 0; q < M; ++q) r += (a[q] > mine) ? 1 : 0;

        int fi  = (int)(~(unsigned)(mine & 0xffffffffu));
        float sc = __uint_as_float((unsigned)(mine >> 32));
        int kk  = fi % C;
        int rem = fi / C;
        int jj  = rem % W;
        int ii  = rem / W;
        const float* p = y + ((size_t)((b * H + ii) * W + jj)) * CP;
        float whx = 4.0f * (expf(p[C])     - 1.0f);
        float why = 4.0f * (expf(p[C + 1]) - 1.0f);
        float cx  = 4.0f * (float)jj + p[C + 2];
        float cy  = 4.0f * (float)ii + p[C + 3];

        score_out[b * K + r] = sc;
        k_out[b * K + r]     = (float)kk;
        c_out[(b * K + r) * 2 + 0] = cx;
        c_out[(b * K + r) * 2 + 1] = cy;
        w_out[(b * K + r) * 2 + 0] = whx;
        w_out[(b * K + r) * 2 + 1] = why;
    }

    for (int r = M + tid; r < K; r += 512) {     // degenerate pad only
        score_out[b * K + r] = 0.0f;
        k_out[b * K + r]     = 0.0f;
        c_out[(b * K + r) * 2 + 0] = 0.0f;
        c_out[(b * K + r) * 2 + 1] = 0.0f;
        w_out[(b * K + r) * 2 + 0] = 0.0f;
        w_out[(b * K + r) * 2 + 1] = 0.0f;
    }

    // reset per-replay counter
    __syncthreads();
    if (tid == 0) g_cnt[b * 32] = 0;
}

extern "C" void kernel_launch(void* const* d_in, const int* in_sizes, int n_in,
                              void* d_out, int out_size) {
    const float* yp = (const float*)d_in[0];
    float* out = (float*)d_out;

    int total = B * H * W * (C / 4);             // 8,192,000 threads
    peaks_kernel<<<total / 256, 256>>>(yp);
    select_kernel<<<B, 512>>>(yp, out);
}

// round 6
// speedup vs baseline: 2.1815x; 1.0585x over previous
#include <cuda_runtime.h>
#include <math.h>

#define B 64
#define H 80
#define W 80
#define C 80
#define CP 84
#define K 100
#define HI_MAX 16384
#define LO_MAX 131072
#define NBINS 8192       // key>>18; positive float keys < 0x7F800000 -> bin < 8160
#define EQCAP 1024
#define CUTOFF 2.5f      // hi list: score > CUTOFF. Exact: if n_hi>=K, top-K in hi.

// pk = (float_bits(score) << 32) | ~sidx : plain u64 '>' == (score desc, idx asc),
// matching jax stable argsort of -score.
__device__ unsigned long long g_hi[B][HI_MAX];
__device__ unsigned long long g_lo[B][LO_MAX];
__device__ int g_hcnt[B * 32];
__device__ int g_lcnt[B * 32];

// ---------------------------------------------------------------------------
// K1: 3x3 NMS peaks. One thread = 4 rows x 4 channels at one column j.
// Separable column-max: 18 float4 loads per 16 outputs (halves L2 traffic).
// threads = B*(H/4)*W*(C/4) = 2,048,000; blocks have uniform b (125/batch).
__global__ void peaks_kernel(const float* __restrict__ y) {
    __shared__ int s_tot;      // packed hi<<16 | lo
    __shared__ int s_hbase, s_lbase;
    if (threadIdx.x == 0) s_tot = 0;
    __syncthreads();

    int t  = blockIdx.x * blockDim.x + threadIdx.x;
    int cg = t % (C / 4);
    int j  = (t / (C / 4)) % W;
    int iq = (t / (W * (C / 4))) % (H / 4);
    int b  = t / ((H / 4) * W * (C / 4));
    int c0 = cg * 4;
    int i0 = iq * 4;

    const float NEGF = __int_as_float(0xff800000);
    const size_t rowS = (size_t)W * CP;
    const float* bbase = y + (size_t)b * H * rowS + c0;

    float4 m[4], v[4];
    #pragma unroll
    for (int r = 0; r < 4; ++r) m[r] = make_float4(NEGF, NEGF, NEGF, NEGF);

    #pragma unroll
    for (int dj = -1; dj <= 1; ++dj) {
        int jj = j + dj;
        bool jok = (jj >= 0) && (jj < W);
        float4 row[6];
        #pragma unroll
        for (int r6 = 0; r6 < 6; ++r6) {
            int ii = i0 - 1 + r6;
            bool ok = jok && (ii >= 0) && (ii < H);
            row[r6] = ok ? *(const float4*)(bbase + (size_t)ii * rowS + (size_t)jj * CP)
                         : make_float4(NEGF, NEGF, NEGF, NEGF);
        }
        #pragma unroll
        for (int r = 0; r < 4; ++r) {
            m[r].x = fmaxf(m[r].x, fmaxf(fmaxf(row[r].x, row[r+1].x), row[r+2].x));
            m[r].y = fmaxf(m[r].y, fmaxf(fmaxf(row[r].y, row[r+1].y), row[r+2].y));
            m[r].z = fmaxf(m[r].z, fmaxf(fmaxf(row[r].z, row[r+1].z), row[r+2].z));
            m[r].w = fmaxf(m[r].w, fmaxf(fmaxf(row[r].w, row[r+1].w), row[r+2].w));
        }
        if (dj == 0) {
            #pragma unroll
            for (int r = 0; r < 4; ++r) v[r] = row[r + 1];
        }
    }

    // predicate masks (recompute pk at write time to keep registers lean)
    unsigned pm = 0, hm = 0;   // bit r*4+q
    #pragma unroll
    for (int r = 0; r < 4; ++r) {
        float vr[4] = {v[r].x, v[r].y, v[r].z, v[r].w};
        float mr[4] = {m[r].x, m[r].y, m[r].z, m[r].w};
        #pragma unroll
        for (int q = 0; q < 4; ++q) {
            if (vr[q] == mr[q] && vr[q] > 0.0f) {
                pm |= 1u << (r * 4 + q);
                if (vr[q] > CUTOFF) hm |= 1u << (r * 4 + q);
            }
        }
    }
    int cnt_hi = __popc(hm);
    int cnt_lo = __popc(pm) - cnt_hi;

    // packed warp prefix + one pair of global atomics per block
    int lane = threadIdx.x & 31;
    int packed = (cnt_hi << 16) | cnt_lo;
    int incl = packed;
    #pragma unroll
    for (int d = 1; d < 32; d <<= 1) {
        int o = __shfl_up_sync(0xffffffffu, incl, d);
        if (lane >= d) incl += o;
    }
    int wtot = __shfl_sync(0xffffffffu, incl, 31);
    int wbase = 0;
    if (lane == 31 && wtot > 0) wbase = atomicAdd(&s_tot, wtot);
    wbase = __shfl_sync(0xffffffffu, wbase, 31);
    __syncthreads();
    if (threadIdx.x == 0) {
        int bt = s_tot;
        s_hbase = (bt >> 16)    ? atomicAdd(&g_hcnt[b * 32], bt >> 16)    : 0;
        s_lbase = (bt & 0xffff) ? atomicAdd(&g_lcnt[b * 32], bt & 0xffff) : 0;
    }
    __syncthreads();

    if (pm) {
        int excl = incl - packed;
        int off_hi = s_hbase + ((wbase + excl) >> 16);
        int off_lo = s_lbase + ((wbase + excl) & 0xffff);
        #pragma unroll
        for (int r = 0; r < 4; ++r) {
            float vr[4] = {v[r].x, v[r].y, v[r].z, v[r].w};
            #pragma unroll
            for (int q = 0; q < 4; ++q) {
                unsigned bit = 1u << (r * 4 + q);
                if (pm & bit) {
                    unsigned key = __float_as_uint(vr[q]);
                    unsigned sidx = (unsigned)(((i0 + r) * W + j) * C + c0 + q);
                    unsigned long long pk =
                        ((unsigned long long)key << 32) | (unsigned)(~sidx);
                    if (hm & bit) {
                        if (off_hi < HI_MAX) g_hi[b][off_hi] = pk;
                        off_hi++;
                    } else {
                        if (off_lo < LO_MAX) g_lo[b][off_lo] = pk;
                        off_lo++;
                    }
                }
            }
        }
    }
}

// ---------------------------------------------------------------------------
// K2: one block per batch: smem histogram -> exact K-th threshold bin ->
// compact (> and ==) -> exact rank -> gather -> emit. Normally only the
// small hi list is scanned; falls back to hi+lo if n_hi < K (exactness).
__global__ void __launch_bounds__(512) select_kernel(const float* __restrict__ y,
                                                     float* __restrict__ out) {
    __shared__ int hist[NBINS];                 // 32KB
    __shared__ unsigned long long se[EQCAP];    // 8KB
    __shared__ unsigned long long a[K];
    __shared__ int csums[512];
    __shared__ int s_tbin, s_cA, s_cE;

    int b   = blockIdx.x;
    int tid = threadIdx.x;                      // 512
    int n_hi = g_hcnt[b * 32]; if (n_hi > HI_MAX) n_hi = HI_MAX;
    int n_lo = g_lcnt[b * 32]; if (n_lo > LO_MAX) n_lo = LO_MAX;
    bool use_lo = (n_hi < K);                   // exact fallback
    int n2 = use_lo ? n_lo : 0;

    const unsigned long long* hi = g_hi[b];
    const unsigned long long* lo = g_lo[b];

    #pragma unroll
    for (int i = tid; i < NBINS; i += 512) hist[i] = 0;
    if (tid == 0) { s_cA = 0; s_cE = 0; }
    __syncthreads();

    // pass 1: histogram of key>>18
    for (int p = tid; p < n_hi; p += 512) atomicAdd(&hist[(int)(hi[p] >> 50)], 1);
    for (int p = tid; p < n2;   p += 512) atomicAdd(&hist[(int)(lo[p] >> 50)], 1);
    __syncthreads();

    {
        int s = 0, base = tid * 16;
        #pragma unroll
        for (int q = 0; q < 16; ++q) s += hist[base + q];
        csums[tid] = s;
    }
    __syncthreads();

    if (tid == 0) {
        int acc = 0, tb = -1;
        for (int c = 511; c >= 0; --c) {
            if (acc + csums[c] >= K) {
                int base = c * 16;
                for (int q = 15; q >= 0; --q) {
                    int h = hist[base + q];
                    if (acc + h >= K) { tb = base + q; break; }
                    acc += h;
                }
                break;
            }
            acc += csums[c];
        }
        s_tbin = tb;          // -1 => total < K: take everything
    }
    __syncthreads();
    int tb = s_tbin;

    // pass 2: compact into above-list (<K) and tie-list
    for (int seg = 0; seg < 2; ++seg) {
        const unsigned long long* src = seg ? lo : hi;
        int n = seg ? n2 : n_hi;
        for (int p = tid; p < n; p += 512) {
            unsigned long long pk = src[p];
            int bin = (int)(pk >> 50);
            if (bin > tb) {
                int q = atomicAdd(&s_cA, 1);
                if (q < K) a[q] = pk;
            } else if (bin == tb) {
                int q = atomicAdd(&s_cE, 1);
                if (q < EQCAP) se[q] = pk;
            }
        }
    }
    __syncthreads();

    int mA = s_cA; if (mA > K) mA = K;
    int nE = s_cE; if (nE > EQCAP) nE = EQCAP;
    int take = K - mA; if (take > nE) take = nE;

    // ties: top 'take' by (score desc, idx asc) == largest packed
    for (int e = tid; e < nE; e += 512) {
        unsigned long long mine = se[e];
        int r = 0;
        for (int q = 0; q < nE; ++q) r += (se[q] > mine) ? 1 : 0;
        if (r < take) a[mA + r] = mine;
    }
    __syncthreads();

    int M = mA + take;                           // == K normally

    float* score_out = out;
    float* k_out     = out + B * K;
    float* c_out     = out + 2 * B * K;
    float* w_out     = out + 4 * B * K;

    if (tid < M) {
        unsigned long long mine = a[tid];
        int r = 0;
        for (int q = 0; q < M; ++q) r += (a[q] > mine) ? 1 : 0;

        int fi  = (int)(~(unsigned)(mine & 0xffffffffu));
        float sc = __uint_as_float((unsigned)(mine >> 32));
        int kk  = fi % C;
        int rem = fi / C;
        int jj  = rem % W;
        int ii  = rem / W;
        const float* p = y + ((size_t)((b * H + ii) * W + jj)) * CP;
        float whx = 4.0f * (expf(p[C])     - 1.0f);
        float why = 4.0f * (expf(p[C + 1]) - 1.0f);
        float cx  = 4.0f * (float)jj + p[C + 2];
        float cy  = 4.0f * (float)ii + p[C + 3];

        score_out[b * K + r] = sc;
        k_out[b * K + r]     = (float)kk;
        c_out[(b * K + r) * 2 + 0] = cx;
        c_out[(b * K + r) * 2 + 1] = cy;
        w_out[(b * K + r) * 2 + 0] = whx;
        w_out[(b * K + r) * 2 + 1] = why;
    }

    for (int r = M + tid; r < K; r += 512) {     // degenerate pad only
        score_out[b * K + r] = 0.0f;
        k_out[b * K + r]     = 0.0f;
        c_out[(b * K + r) * 2 + 0] = 0.0f;
        c_out[(b * K + r) * 2 + 1] = 0.0f;
        w_out[(b * K + r) * 2 + 0] = 0.0f;
        w_out[(b * K + r) * 2 + 1] = 0.0f;
    }

    __syncthreads();
    if (tid == 0) { g_hcnt[b * 32] = 0; g_lcnt[b * 32] = 0; }
}

extern "C" void kernel_launch(void* const* d_in, const int* in_sizes, int n_in,
                              void* d_out, int out_size) {
    const float* yp = (const float*)d_in[0];
    float* out = (float*)d_out;

    int total = B * (H / 4) * W * (C / 4);       // 2,048,000 threads
    peaks_kernel<<<total / 256, 256>>>(yp);
    select_kernel<<<B, 512>>>(yp, out);
}

// round 7
// speedup vs baseline: 3.5614x; 1.6325x over previous
#include <cuda_runtime.h>
#include <math.h>

#define B 64
#define H 80
#define W 80
#define C 80
#define CP 84
#define K 100
#define JS 10            // columns per thread strip (W/JS = 8 strips)
#define HI_MAX 16384
#define LO_MAX 131072
#define NBINS 8192       // key>>18; positive float keys < 0x7F800000 -> bin < 8160
#define EQCAP 1024
#define CUTOFF_BITS 0x40200000u   // __float_as_uint(2.5f); key > bits <=> score > 2.5

// pk = (float_bits(score) << 32) | ~sidx : plain u64 '>' == (score desc, idx asc),
// matching jax stable argsort of -score.
__device__ unsigned long long g_hi[B][HI_MAX];
__device__ unsigned long long g_lo[B][LO_MAX];
__device__ int g_hcnt[B * 32];
__device__ int g_lcnt[B * 32];

__device__ __forceinline__ float4 max4(float4 a, float4 b) {
    return make_float4(fmaxf(a.x, b.x), fmaxf(a.y, b.y),
                       fmaxf(a.z, b.z), fmaxf(a.w, b.w));
}

// ---------------------------------------------------------------------------
// K1: 3x3 NMS peaks, sliding window along j.
// One thread = 4 channels x 1 row x JS columns. Per column step: 3 float4
// loads (rows i-1,i,i+1) -> running column maxes in registers.
// threads = B*H*(W/JS)*(C/4) = 819,200; 12800/batch -> blocks uniform in b.
__global__ void __launch_bounds__(256) peaks_kernel(const float* __restrict__ y) {
    __shared__ int s_tot;      // packed hi<<16 | lo
    __shared__ int s_hbase, s_lbase;
    if (threadIdx.x == 0) s_tot = 0;
    __syncthreads();

    int t  = blockIdx.x * 256 + threadIdx.x;
    int cg = t % (C / 4);                 // 20
    int st = (t / (C / 4)) % (W / JS);    // 8
    int i  = (t / ((C / 4) * (W / JS))) % H;
    int b  = t / ((C / 4) * (W / JS) * H);
    int c0 = cg * 4;
    int j0 = st * JS;

    const float NEGF = __int_as_float(0xff800000);
    const float4 NEG4 = make_float4(NEGF, NEGF, NEGF, NEGF);
    const size_t rowS = (size_t)W * CP;
    const float* rowp = y + ((size_t)(b * H + i)) * rowS + c0;
    bool up = (i > 0), dn = (i < H - 1);

    unsigned long long cand[JS * 4];
    int nc = 0;

    float4 cma, cmb, cmc, cvb, cvc;

    // column j0-1
    {
        int jj = j0 - 1;
        if (jj >= 0) {
            const float* p = rowp + (size_t)jj * CP;
            float4 a = up ? *(const float4*)(p - rowS) : NEG4;
            float4 c = *(const float4*)p;
            float4 d = dn ? *(const float4*)(p + rowS) : NEG4;
            cma = max4(max4(a, d), c);
        } else cma = NEG4;
    }
    // column j0
    {
        const float* p = rowp + (size_t)j0 * CP;
        float4 a = up ? *(const float4*)(p - rowS) : NEG4;
        float4 c = *(const float4*)p;
        float4 d = dn ? *(const float4*)(p + rowS) : NEG4;
        cmb = max4(max4(a, d), c);
        cvb = c;
    }

    #pragma unroll
    for (int jo = 0; jo < JS; ++jo) {
        int j = j0 + jo;
        int jj = j + 1;
        if (jj < W) {
            const float* p = rowp + (size_t)jj * CP;
            float4 a = up ? *(const float4*)(p - rowS) : NEG4;
            float4 c = *(const float4*)p;
            float4 d = dn ? *(const float4*)(p + rowS) : NEG4;
            cmc = max4(max4(a, d), c);
            cvc = c;
        } else { cmc = NEG4; cvc = NEG4; }

        float4 mx = max4(max4(cma, cmc), cmb);
        float vr[4] = {cvb.x, cvb.y, cvb.z, cvb.w};
        float mr[4] = {mx.x, mx.y, mx.z, mx.w};
        int sidx = (i * W + j) * C + c0;
        #pragma unroll
        for (int q = 0; q < 4; ++q) {
            if (vr[q] == mr[q] && vr[q] > 0.0f) {
                unsigned key = __float_as_uint(vr[q]);
                cand[nc++] = ((unsigned long long)key << 32)
                           | (unsigned)(~(unsigned)(sidx + q));
            }
        }
        cma = cmb; cmb = cmc; cvb = cvc;
    }

    // split counts
    int cnt_hi = 0;
    for (int q = 0; q < nc; ++q)
        cnt_hi += ((unsigned)(cand[q] >> 32) > CUTOFF_BITS) ? 1 : 0;
    int cnt_lo = nc - cnt_hi;

    // packed warp prefix + one pair of global atomics per block
    int lane = threadIdx.x & 31;
    int packed = (cnt_hi << 16) | cnt_lo;
    int incl = packed;
    #pragma unroll
    for (int d = 1; d < 32; d <<= 1) {
        int o = __shfl_up_sync(0xffffffffu, incl, d);
        if (lane >= d) incl += o;
    }
    int wtot = __shfl_sync(0xffffffffu, incl, 31);
    int wbase = 0;
    if (lane == 31 && wtot > 0) wbase = atomicAdd(&s_tot, wtot);
    wbase = __shfl_sync(0xffffffffu, wbase, 31);
    __syncthreads();
    if (threadIdx.x == 0) {
        int bt = s_tot;
        s_hbase = (bt >> 16)    ? atomicAdd(&g_hcnt[b * 32], bt >> 16)    : 0;
        s_lbase = (bt & 0xffff) ? atomicAdd(&g_lcnt[b * 32], bt & 0xffff) : 0;
    }
    __syncthreads();

    if (nc > 0) {
        int excl = incl - packed;
        int off_hi = s_hbase + ((wbase + excl) >> 16);
        int off_lo = s_lbase + ((wbase + excl) & 0xffff);
        for (int q = 0; q < nc; ++q) {
            unsigned long long pk = cand[q];
            if ((unsigned)(pk >> 32) > CUTOFF_BITS) {
                if (off_hi < HI_MAX) g_hi[b][off_hi] = pk;
                off_hi++;
            } else {
                if (off_lo < LO_MAX) g_lo[b][off_lo] = pk;
                off_lo++;
            }
        }
    }
}

// ---------------------------------------------------------------------------
// K2: one block per batch: smem histogram -> exact K-th threshold bin ->
// compact (> and ==) -> exact rank -> gather -> emit. Normally only the
// small hi list is scanned; exact fallback to hi+lo if n_hi < K.
__global__ void __launch_bounds__(512) select_kernel(const float* __restrict__ y,
                                                     float* __restrict__ out) {
    __shared__ int hist[NBINS];                 // 32KB
    __shared__ unsigned long long se[EQCAP];    // 8KB
    __shared__ unsigned long long a[K];
    __shared__ int csums[512];
    __shared__ int s_tbin, s_cA, s_cE;

    int b   = blockIdx.x;
    int tid = threadIdx.x;                      // 512
    int n_hi = g_hcnt[b * 32]; if (n_hi > HI_MAX) n_hi = HI_MAX;
    int n_lo = g_lcnt[b * 32]; if (n_lo > LO_MAX) n_lo = LO_MAX;
    bool use_lo = (n_hi < K);                   // exact fallback
    int n2 = use_lo ? n_lo : 0;

    const unsigned long long* hi = g_hi[b];
    const unsigned long long* lo = g_lo[b];

    #pragma unroll
    for (int i = tid; i < NBINS; i += 512) hist[i] = 0;
    if (tid == 0) { s_cA = 0; s_cE = 0; s_tbin = -1; }
    __syncthreads();

    // pass 1: histogram of key>>18
    for (int p = tid; p < n_hi; p += 512) atomicAdd(&hist[(int)(hi[p] >> 50)], 1);
    for (int p = tid; p < n2;   p += 512) atomicAdd(&hist[(int)(lo[p] >> 50)], 1);
    __syncthreads();

    {
        int s = 0, base = tid * 16;
        #pragma unroll
        for (int q = 0; q < 16; ++q) s += hist[base + q];
        csums[tid] = s;
    }
    __syncthreads();

    // parallel threshold: warp 0, 32 segments of 16 csums
    if (tid < 32) {
        int seg = 0, base = tid * 16;
        #pragma unroll
        for (int q = 0; q < 16; ++q) seg += csums[base + q];
        int x = seg;
        #pragma unroll
        for (int d = 1; d < 32; d <<= 1) {
            int o = __shfl_down_sync(0xffffffffu, x, d);
            if (tid + d < 32) x += o;
        }
        int suf_excl = x - seg;                  // total in segments above mine
        if (suf_excl < K && suf_excl + seg >= K) {
            int acc = suf_excl;
            for (int c = base + 15; c >= base; --c) {
                int h = csums[c];
                if (acc + h >= K) {
                    for (int q = c * 16 + 15; q >= c * 16; --q) {
                        int hb2 = hist[q];
                        if (acc + hb2 >= K) { s_tbin = q; break; }
                        acc += hb2;
                    }
                    break;
                }
                acc += h;
            }
        }
    }
    __syncthreads();
    int tb = s_tbin;                             // -1 => total < K: take everything

    // pass 2: compact into above-list (<K) and tie-list
    for (int seg = 0; seg < 2; ++seg) {
        const unsigned long long* src = seg ? lo : hi;
        int n = seg ? n2 : n_hi;
        for (int p = tid; p < n; p += 512) {
            unsigned long long pk = src[p];
            int bin = (int)(pk >> 50);
            if (bin > tb) {
                int q = atomicAdd(&s_cA, 1);
                if (q < K) a[q] = pk;
            } else if (bin == tb) {
                int q = atomicAdd(&s_cE, 1);
                if (q < EQCAP) se[q] = pk;
            }
        }
    }
    __syncthreads();

    int mA = s_cA; if (mA > K) mA = K;
    int nE = s_cE; if (nE > EQCAP) nE = EQCAP;
    int take = K - mA; if (take > nE) take = nE;

    // ties: top 'take' by (score desc, idx asc) == largest packed
    for (int e = tid; e < nE; e += 512) {
        unsigned long long mine = se[e];
        int r = 0;
        for (int q = 0; q < nE; ++q) r += (se[q] > mine) ? 1 : 0;
        if (r < take) a[mA + r] = mine;
    }
    __syncthreads();

    int M = mA + take;                           // == K normally

    float* score_out = out;
    float* k_out     = out + B * K;
    float* c_out     = out + 2 * B * K;
    float* w_out     = out + 4 * B * K;

    if (tid < M) {
        unsigned long long mine = a[tid];
        int r = 0;
        for (int q = 0; q < M; ++q) r += (a[q] > mine) ? 1 : 0;

        int fi  = (int)(~(unsigned)(mine & 0xffffffffu));
        float sc = __uint_as_float((unsigned)(mine >> 32));
        int kk  = fi % C;
        int rem = fi / C;
        int jj  = rem % W;
        int ii  = rem / W;
        const float* p = y + ((size_t)((b * H + ii) * W + jj)) * CP;
        float whx = 4.0f * (expf(p[C])     - 1.0f);
        float why = 4.0f * (expf(p[C + 1]) - 1.0f);
        float cx  = 4.0f * (float)jj + p[C + 2];
        float cy  = 4.0f * (float)ii + p[C + 3];

        score_out[b * K + r] = sc;
        k_out[b * K + r]     = (float)kk;
        c_out[(b * K + r) * 2 + 0] = cx;
        c_out[(b * K + r) * 2 + 1] = cy;
        w_out[(b * K + r) * 2 + 0] = whx;
        w_out[(b * K + r) * 2 + 1] = why;
    }

    for (int r = M + tid; r < K; r += 512) {     // degenerate pad only
        score_out[b * K + r] = 0.0f;
        k_out[b * K + r]     = 0.0f;
        c_out[(b * K + r) * 2 + 0] = 0.0f;
        c_out[(b * K + r) * 2 + 1] = 0.0f;
        w_out[(b * K + r) * 2 + 0] = 0.0f;
        w_out[(b * K + r) * 2 + 1] = 0.0f;
    }

    __syncthreads();
    if (tid == 0) { g_hcnt[b * 32] = 0; g_lcnt[b * 32] = 0; }
}

extern "C" void kernel_launch(void* const* d_in, const int* in_sizes, int n_in,
                              void* d_out, int out_size) {
    const float* yp = (const float*)d_in[0];
    float* out = (float*)d_out;

    int total = B * H * (W / JS) * (C / 4);      // 819,200 threads
    peaks_kernel<<<total / 256, 256>>>(yp);
    select_kernel<<<B, 512>>>(yp, out);
}